// round 12
// baseline (speedup 1.0000x reference)
#include <cuda_runtime.h>
#include <cuda_fp16.h>
#include <cstdint>
#include <math.h>

// ---------------- problem dims ----------------
#define C_DIM  16
#define B_DIM  4096
#define N_DIM  32768           // C * 2H
#define K_HALF 1024

#define X_ELEMS (B_DIM * K_HALF)      //  4 M
#define W_ELEMS (N_DIM * K_HALF)      // 32 M

// ---------------- tiling ----------------
#define BM 128
#define BN 64
#define BKE 64                 // K elements per slab (64 halves = 128B row)
#define NSTAGE 3
#define NITER 32               // 2048 / 64

#define A_TILE_BYTES (BM * 128)        // 16384
#define B_TILE_BYTES (BN * 128)        //  8192
#define STAGE_BYTES  (A_TILE_BYTES + B_TILE_BYTES)   // 24576
#define SMEM_TOTAL   (NSTAGE * STAGE_BYTES)          // 73728

static const size_t HALF_OUT = (size_t)B_DIM * C_DIM * 1024;

// ---------------- f16 scratch (device globals: allowed) ----------------
__device__ __half g_X[X_ELEMS];
__device__ __half g_H[X_ELEMS];
__device__ __half g_Wx[W_ELEMS];
__device__ __half g_Wh[W_ELEMS];

__device__ __forceinline__ uint32_t smem_u32(const void* p) {
    uint32_t a;
    asm("{ .reg .u64 t; cvta.to.shared.u64 t, %1; cvt.u32.u64 %0, t; }" : "=r"(a) : "l"(p));
    return a;
}

#define CP_ASYNC16(dst, src) \
    asm volatile("cp.async.cg.shared.global [%0], [%1], 16;" :: "r"(dst), "l"(src))
#define CP_COMMIT() asm volatile("cp.async.commit_group;")
#define CP_WAIT1()  asm volatile("cp.async.wait_group 1;")

#define LDSM_X4(r0, r1, r2, r3, a) \
    asm volatile("ldmatrix.sync.aligned.m8n8.x4.shared.b16 {%0,%1,%2,%3}, [%4];" \
                 : "=r"(r0), "=r"(r1), "=r"(r2), "=r"(r3) : "r"(a))

// m16n8k16 f16 MMA, fp32 accumulate
#define MMA_F16(c, a, b0, b1)                                                    \
    asm volatile("mma.sync.aligned.m16n8k16.row.col.f32.f16.f16.f32 "            \
                 "{%0,%1,%2,%3}, {%4,%5,%6,%7}, {%8,%9}, {%0,%1,%2,%3};"         \
                 : "+f"((c)[0]), "+f"((c)[1]), "+f"((c)[2]), "+f"((c)[3])        \
                 : "r"((a)[0]), "r"((a)[1]), "r"((a)[2]), "r"((a)[3]),           \
                   "r"(b0), "r"(b1))

// ---------------- prep: f32 -> f16 (rn), 8 elems per thread ----------------
__global__ void __launch_bounds__(256)
prep_f16_kernel(const float4* __restrict__ src, uint4* __restrict__ dst, int n8) {
    int i = blockIdx.x * blockDim.x + threadIdx.x;
    if (i < n8) {
        float4 v0 = src[2 * i], v1 = src[2 * i + 1];
        __half2 h0 = __floats2half2_rn(v0.x, v0.y);
        __half2 h1 = __floats2half2_rn(v0.z, v0.w);
        __half2 h2 = __floats2half2_rn(v1.x, v1.y);
        __half2 h3 = __floats2half2_rn(v1.z, v1.w);
        uint4 o;
        o.x = *(uint32_t*)&h0; o.y = *(uint32_t*)&h1;
        o.z = *(uint32_t*)&h2; o.w = *(uint32_t*)&h3;
        dst[i] = o;
    }
}

// ---------------- main GEMM: f16 m16n8k16, 32x32 warp tiles, 3 CTAs/SM ----
__global__ void __launch_bounds__(256, 3)
gate_mma_kernel(const __half* __restrict__ Xh,   // [4096, 1024]
                const __half* __restrict__ Hh,   // [4096, 1024]
                const __half* __restrict__ Wxh,  // [32768, 1024]
                const float*  __restrict__ bx,   // [32768]
                const __half* __restrict__ Whh,  // [32768, 1024]
                float* __restrict__ out)
{
    extern __shared__ char smem[];
    const uint32_t sb = smem_u32(smem);

    const int tid  = threadIdx.x;
    const int lane = tid & 31;
    const int warp = tid >> 5;
    const int wm   = warp >> 1;          // 0..3  (M direction, 4 x 32 rows)
    const int wn   = warp & 1;           // 0..1  (N direction, 2 x 32 cols)

    const int bm = blockIdx.x * BM;      // M fastest: A tiles L2-resident
    const int bn = blockIdx.y * BN;

    // ---- cp.async mapping ----
    const int lm = tid >> 1;             // A row 0..127
    const int lk = (tid & 1) * 4;        // A chunk base (4 chunks of 16B)
    const int bl = tid >> 2;             // B row 0..63
    const int bk = (tid & 3) * 2;        // B chunk base (2 chunks of 16B)

    // ---- ldmatrix per-lane address pieces (chunk = 16B = 8 halves = K8) ----
    const int l7 = lane & 7;
    const int am_off = l7 + ((lane >> 3) & 1) * 8;   // A rows: q1,q3 -> +8
    const int aq     = (lane >> 4) & 1;              // A: q2,q3 -> chunk+1
    const int bn_off = l7 + ((lane >> 4) & 1) * 8;   // B rows: q2,q3 -> +8
    const int bq     = (lane >> 3) & 1;              // B: q1,q3 -> chunk+1

    float acc[2][4][4];
    #pragma unroll
    for (int i = 0; i < 2; i++)
        #pragma unroll
        for (int j = 0; j < 4; j++)
            #pragma unroll
            for (int k = 0; k < 4; k++)
                acc[i][j][k] = 0.f;

    // ---- stage loader (write swizzle keyed on DEST ROW) ----
    auto load_stage = [&](int s, int it) {
        const __half* Ab = (it < 16) ? Xh : Hh;
        const __half* Bb = (it < 16) ? Wxh : Whh;
        const int k0 = (it & 15) * BKE;
        const __half* asrc = Ab + (size_t)(bm + lm) * K_HALF + k0;
        const __half* bsrc = Bb + (size_t)(bn + bl) * K_HALF + k0;
        const uint32_t arow = sb + s * STAGE_BYTES + lm * 128;
        const uint32_t brow = sb + s * STAGE_BYTES + A_TILE_BYTES + bl * 128;
        #pragma unroll
        for (int j = 0; j < 4; j++) {
            const int kc = lk + j;
            CP_ASYNC16(arow + ((kc ^ (lm & 7)) << 4), asrc + kc * 8);
        }
        #pragma unroll
        for (int j = 0; j < 2; j++) {
            const int kc = bk + j;
            CP_ASYNC16(brow + ((kc ^ (bl & 7)) << 4), bsrc + kc * 8);
        }
    };

    // ---- prologue ----
    load_stage(0, 0); CP_COMMIT();
    load_stage(1, 1); CP_COMMIT();

    // ---- mainloop: one barrier per iteration ----
    #pragma unroll 1
    for (int it = 0; it < NITER; it++) {
        CP_WAIT1();
        __syncthreads();   // all warps done reading stage (it-1): safe to refill

        if (it + 2 < NITER) load_stage((it + 2) % NSTAGE, it + 2);
        CP_COMMIT();       // empty groups keep wait_group(1) semantics exact

        const int s = it % NSTAGE;
        const uint32_t a_base = sb + s * STAGE_BYTES;
        const uint32_t b_base = a_base + A_TILE_BYTES;

        #pragma unroll
        for (int ks = 0; ks < 4; ks++) {     // 4 x K16 = K64 per stage
            uint32_t ar[2][4], br[2][4];
            #pragma unroll
            for (int mf = 0; mf < 2; mf++) {
                const int m = wm * 32 + mf * 16 + am_off;
                const uint32_t addr = a_base + m * 128 + (((2 * ks + aq) ^ (m & 7)) << 4);
                LDSM_X4(ar[mf][0], ar[mf][1], ar[mf][2], ar[mf][3], addr);
            }
            #pragma unroll
            for (int j = 0; j < 2; j++) {
                const int n = wn * 32 + j * 16 + bn_off;
                const uint32_t addr = b_base + n * 128 + (((2 * ks + bq) ^ (n & 7)) << 4);
                LDSM_X4(br[j][0], br[j][1], br[j][2], br[j][3], addr);
            }
            #pragma unroll
            for (int mf = 0; mf < 2; mf++) {
                #pragma unroll
                for (int nf = 0; nf < 4; nf++) {
                    const int j = nf >> 1, h = (nf & 1) * 2;
                    MMA_F16(acc[mf][nf], ar[mf], br[j][h], br[j][h + 1]);
                }
            }
        }
    }

    // ---- epilogue: bias + activation + scatter ----
    const int  c_blk   = bn >> 11;
    const bool is_gate = (bn & 2047) < 1024;        // sigmoid half -> input_gate
    const int  o_tile  = bn & 1023;
    float* obase = is_gate ? (out + HALF_OUT) : out;

    #pragma unroll
    for (int mf = 0; mf < 2; mf++) {
        const int m0 = bm + wm * 32 + mf * 16 + (lane >> 2);
        #pragma unroll
        for (int nf = 0; nf < 4; nf++) {
            const int n_loc = wn * 32 + nf * 8 + (lane & 3) * 2;
            const float b0 = __ldg(bx + bn + n_loc);
            const float b1 = __ldg(bx + bn + n_loc + 1);
            const int o = o_tile + n_loc;
            #pragma unroll
            for (int h = 0; h < 2; h++) {            // rows m0, m0+8
                const int m = m0 + h * 8;
                float x0 = acc[mf][nf][h * 2 + 0] + b0;
                float x1 = acc[mf][nf][h * 2 + 1] + b1;
                float2 v;
                if (is_gate) {
                    v.x = 1.f / (1.f + __expf(-x0));
                    v.y = 1.f / (1.f + __expf(-x1));
                } else {
                    v.x = 2.f / (1.f + __expf(-2.f * x0)) - 1.f;
                    v.y = 2.f / (1.f + __expf(-2.f * x1)) - 1.f;
                }
                *(float2*)(obase + ((size_t)m * C_DIM + c_blk) * 1024 + o) = v;
            }
        }
    }
}

extern "C" void kernel_launch(void* const* d_in, const int* in_sizes, int n_in,
                              void* d_out, int out_size) {
    const float* input_word = (const float*)d_in[0];
    const float* hidden     = (const float*)d_in[1];
    const float* Wx         = (const float*)d_in[2];
    const float* bx         = (const float*)d_in[3];
    const float* Wh         = (const float*)d_in[4];

    __half *pX, *pH, *pWx, *pWh;
    cudaGetSymbolAddress((void**)&pX,  g_X);
    cudaGetSymbolAddress((void**)&pH,  g_H);
    cudaGetSymbolAddress((void**)&pWx, g_Wx);
    cudaGetSymbolAddress((void**)&pWh, g_Wh);
    cudaFuncSetAttribute(gate_mma_kernel,
                         cudaFuncAttributeMaxDynamicSharedMemorySize, SMEM_TOTAL);

    // prep: f32 -> f16 copies (memory-bound, ~60us total)
    prep_f16_kernel<<<X_ELEMS / 8 / 256, 256>>>((const float4*)input_word,
                                                (uint4*)pX, X_ELEMS / 8);
    prep_f16_kernel<<<X_ELEMS / 8 / 256, 256>>>((const float4*)hidden,
                                                (uint4*)pH, X_ELEMS / 8);
    prep_f16_kernel<<<W_ELEMS / 8 / 256, 256>>>((const float4*)Wx,
                                                (uint4*)pWx, W_ELEMS / 8);
    prep_f16_kernel<<<W_ELEMS / 8 / 256, 256>>>((const float4*)Wh,
                                                (uint4*)pWh, W_ELEMS / 8);

    dim3 grid(B_DIM / BM, N_DIM / BN);   // (32, 512), M fastest
    gate_mma_kernel<<<grid, 256, SMEM_TOTAL>>>(pX, pH, pWx, bx, pWh, (float*)d_out);
}

// round 13
// speedup vs baseline: 1.0686x; 1.0686x over previous
#include <cuda_runtime.h>
#include <cuda_fp16.h>
#include <cstdint>
#include <math.h>

// ---------------- problem dims ----------------
#define C_DIM  16
#define B_DIM  4096
#define N_DIM  32768           // C * 2H
#define K_HALF 1024

#define X_ELEMS (B_DIM * K_HALF)      //  4 M
#define W_ELEMS (N_DIM * K_HALF)      // 32 M

// ---------------- tiling (R11 best shape) ----------------
#define BM 128
#define BN 128
#define BKE 64                 // K elements per slab (64 halves = 128B row)
#define NSTAGE 3
#define NITER 32               // 2048 / 64

#define A_TILE_BYTES (BM * 128)        // 16384
#define B_TILE_BYTES (BN * 128)        // 16384
#define STAGE_BYTES  (A_TILE_BYTES + B_TILE_BYTES)   // 32768
#define SMEM_TOTAL   (NSTAGE * STAGE_BYTES)          // 98304

static const size_t HALF_OUT = (size_t)B_DIM * C_DIM * 1024;

// ---------------- f16 scratch (device globals: allowed) ----------------
__device__ __half g_X[X_ELEMS];
__device__ __half g_H[X_ELEMS];
__device__ __half g_Wx[W_ELEMS];
__device__ __half g_Wh[W_ELEMS];

__device__ __forceinline__ uint32_t smem_u32(const void* p) {
    uint32_t a;
    asm("{ .reg .u64 t; cvta.to.shared.u64 t, %1; cvt.u32.u64 %0, t; }" : "=r"(a) : "l"(p));
    return a;
}

#define CP_ASYNC16(dst, src) \
    asm volatile("cp.async.cg.shared.global [%0], [%1], 16;" :: "r"(dst), "l"(src))
#define CP_COMMIT() asm volatile("cp.async.commit_group;")
#define CP_WAIT1()  asm volatile("cp.async.wait_group 1;")

#define LDSM_X4(r0, r1, r2, r3, a) \
    asm volatile("ldmatrix.sync.aligned.m8n8.x4.shared.b16 {%0,%1,%2,%3}, [%4];" \
                 : "=r"(r0), "=r"(r1), "=r"(r2), "=r"(r3) : "r"(a))

// m16n8k16 f16 MMA, fp32 accumulate
#define MMA_F16(c, a, b0, b1)                                                    \
    asm volatile("mma.sync.aligned.m16n8k16.row.col.f32.f16.f16.f32 "            \
                 "{%0,%1,%2,%3}, {%4,%5,%6,%7}, {%8,%9}, {%0,%1,%2,%3};"         \
                 : "+f"((c)[0]), "+f"((c)[1]), "+f"((c)[2]), "+f"((c)[3])        \
                 : "r"((a)[0]), "r"((a)[1]), "r"((a)[2]), "r"((a)[3]),           \
                   "r"(b0), "r"(b1))

// ---------------- prep: f32 -> f16 (rn), 8 elems per thread ----------------
__global__ void __launch_bounds__(256)
prep_f16_kernel(const float4* __restrict__ src, uint4* __restrict__ dst, int n8) {
    int i = blockIdx.x * blockDim.x + threadIdx.x;
    if (i < n8) {
        float4 v0 = src[2 * i], v1 = src[2 * i + 1];
        __half2 h0 = __floats2half2_rn(v0.x, v0.y);
        __half2 h1 = __floats2half2_rn(v0.z, v0.w);
        __half2 h2 = __floats2half2_rn(v1.x, v1.y);
        __half2 h3 = __floats2half2_rn(v1.z, v1.w);
        uint4 o;
        o.x = *(uint32_t*)&h0; o.y = *(uint32_t*)&h1;
        o.z = *(uint32_t*)&h2; o.w = *(uint32_t*)&h3;
        dst[i] = o;
    }
}

// ------- main GEMM: f16 m16n8k16, 64x32 warp tiles, frag double-buffer -------
__global__ void __launch_bounds__(256, 2)
gate_mma_kernel(const __half* __restrict__ Xh,   // [4096, 1024]
                const __half* __restrict__ Hh,   // [4096, 1024]
                const __half* __restrict__ Wxh,  // [32768, 1024]
                const float*  __restrict__ bx,   // [32768]
                const __half* __restrict__ Whh,  // [32768, 1024]
                float* __restrict__ out)
{
    extern __shared__ char smem[];
    const uint32_t sb = smem_u32(smem);

    const int tid  = threadIdx.x;
    const int lane = tid & 31;
    const int warp = tid >> 5;
    const int wm   = warp >> 2;          // 0..1
    const int wn   = warp & 3;           // 0..3

    const int bm = blockIdx.x * BM;      // M fastest: A tiles L2-resident
    const int bn = blockIdx.y * BN;

    // ---- cp.async mapping ----
    const int lm = tid >> 1;             // tile row 0..127
    const int lk = (tid & 1) * 4;        // chunk base 0 or 4 (of 8 per row)

    // ---- ldmatrix per-lane address pieces (chunk = 16B = 8 halves = K8) ----
    const int l7 = lane & 7;
    const int am_off = l7 + ((lane >> 3) & 1) * 8;   // A rows: q1,q3 -> +8
    const int aq     = (lane >> 4) & 1;              // A: q2,q3 -> chunk+1
    const int bn_off = l7 + ((lane >> 4) & 1) * 8;   // B rows: q2,q3 -> +8
    const int bq     = (lane >> 3) & 1;              // B: q1,q3 -> chunk+1

    float acc[4][4][4];
    #pragma unroll
    for (int i = 0; i < 4; i++)
        #pragma unroll
        for (int j = 0; j < 4; j++)
            #pragma unroll
            for (int k = 0; k < 4; k++)
                acc[i][j][k] = 0.f;

    // ---- stage loader (write swizzle keyed on DEST ROW lm&7) ----
    auto load_stage = [&](int s, int it) {
        const __half* Ab = (it < 16) ? Xh : Hh;
        const __half* Bb = (it < 16) ? Wxh : Whh;
        const int k0 = (it & 15) * BKE;
        const __half* asrc = Ab + (size_t)(bm + lm) * K_HALF + k0;
        const __half* bsrc = Bb + (size_t)(bn + lm) * K_HALF + k0;
        const uint32_t arow = sb + s * STAGE_BYTES + lm * 128;
        const uint32_t brow = sb + s * STAGE_BYTES + A_TILE_BYTES + lm * 128;
        #pragma unroll
        for (int j = 0; j < 4; j++) {
            const int kc = lk + j;
            const int sw = (kc ^ (lm & 7)) << 4;
            CP_ASYNC16(arow + sw, asrc + kc * 8);
            CP_ASYNC16(brow + sw, bsrc + kc * 8);
        }
    };

    // ---- prologue ----
    load_stage(0, 0); CP_COMMIT();
    load_stage(1, 1); CP_COMMIT();

    // double-buffered fragment sets: hide LDSM latency under MMA bursts
    uint32_t ar[2][4][4], br[2][2][4];

    // ---- mainloop: one barrier per iteration ----
    #pragma unroll 1
    for (int it = 0; it < NITER; it++) {
        CP_WAIT1();
        __syncthreads();   // all warps done reading stage (it-1): safe to refill

        if (it + 2 < NITER) load_stage((it + 2) % NSTAGE, it + 2);
        CP_COMMIT();       // empty groups keep wait_group(1) semantics exact

        const int s = it % NSTAGE;
        const uint32_t a_base = sb + s * STAGE_BYTES;
        const uint32_t b_base = a_base + A_TILE_BYTES;

        // preload ks=0 fragments into buffer 0
        #pragma unroll
        for (int mf = 0; mf < 4; mf++) {
            const int m = wm * 64 + mf * 16 + am_off;
            LDSM_X4(ar[0][mf][0], ar[0][mf][1], ar[0][mf][2], ar[0][mf][3],
                    a_base + m * 128 + ((aq ^ l7) << 4));
        }
        #pragma unroll
        for (int j = 0; j < 2; j++) {
            const int n = wn * 32 + j * 16 + bn_off;
            LDSM_X4(br[0][j][0], br[0][j][1], br[0][j][2], br[0][j][3],
                    b_base + n * 128 + ((bq ^ l7) << 4));
        }

        #pragma unroll
        for (int ks = 0; ks < 4; ks++) {     // 4 x K16 = K64 per stage
            const int cur = ks & 1, nxt = cur ^ 1;

            // prefetch ks+1's fragments (overlaps with this ks's MMA burst)
            if (ks < 3) {
                #pragma unroll
                for (int mf = 0; mf < 4; mf++) {
                    const int m = wm * 64 + mf * 16 + am_off;
                    LDSM_X4(ar[nxt][mf][0], ar[nxt][mf][1], ar[nxt][mf][2], ar[nxt][mf][3],
                            a_base + m * 128 + (((2 * (ks + 1) + aq) ^ l7) << 4));
                }
                #pragma unroll
                for (int j = 0; j < 2; j++) {
                    const int n = wn * 32 + j * 16 + bn_off;
                    LDSM_X4(br[nxt][j][0], br[nxt][j][1], br[nxt][j][2], br[nxt][j][3],
                            b_base + n * 128 + (((2 * (ks + 1) + bq) ^ l7) << 4));
                }
            }

            #pragma unroll
            for (int mf = 0; mf < 4; mf++) {
                #pragma unroll
                for (int nf = 0; nf < 4; nf++) {
                    const int j = nf >> 1, h = (nf & 1) * 2;
                    MMA_F16(acc[mf][nf], ar[cur][mf], br[cur][j][h], br[cur][j][h + 1]);
                }
            }
        }
    }

    // ---- epilogue: bias + activation + scatter ----
    const int  c_blk   = bn >> 11;
    const bool is_gate = (bn & 2047) < 1024;        // sigmoid half -> input_gate
    const int  o_tile  = bn & 1023;
    float* obase = is_gate ? (out + HALF_OUT) : out;

    #pragma unroll
    for (int mf = 0; mf < 4; mf++) {
        const int m0 = bm + wm * 64 + mf * 16 + (lane >> 2);
        #pragma unroll
        for (int nf = 0; nf < 4; nf++) {
            const int n_loc = wn * 32 + nf * 8 + (lane & 3) * 2;
            const float b0 = __ldg(bx + bn + n_loc);
            const float b1 = __ldg(bx + bn + n_loc + 1);
            const int o = o_tile + n_loc;
            #pragma unroll
            for (int h = 0; h < 2; h++) {            // rows m0, m0+8
                const int m = m0 + h * 8;
                float x0 = acc[mf][nf][h * 2 + 0] + b0;
                float x1 = acc[mf][nf][h * 2 + 1] + b1;
                float2 v;
                if (is_gate) {
                    v.x = 1.f / (1.f + __expf(-x0));
                    v.y = 1.f / (1.f + __expf(-x1));
                } else {
                    v.x = 2.f / (1.f + __expf(-2.f * x0)) - 1.f;
                    v.y = 2.f / (1.f + __expf(-2.f * x1)) - 1.f;
                }
                *(float2*)(obase + ((size_t)m * C_DIM + c_blk) * 1024 + o) = v;
            }
        }
    }
}

extern "C" void kernel_launch(void* const* d_in, const int* in_sizes, int n_in,
                              void* d_out, int out_size) {
    const float* input_word = (const float*)d_in[0];
    const float* hidden     = (const float*)d_in[1];
    const float* Wx         = (const float*)d_in[2];
    const float* bx         = (const float*)d_in[3];
    const float* Wh         = (const float*)d_in[4];

    __half *pX, *pH, *pWx, *pWh;
    cudaGetSymbolAddress((void**)&pX,  g_X);
    cudaGetSymbolAddress((void**)&pH,  g_H);
    cudaGetSymbolAddress((void**)&pWx, g_Wx);
    cudaGetSymbolAddress((void**)&pWh, g_Wh);
    cudaFuncSetAttribute(gate_mma_kernel,
                         cudaFuncAttributeMaxDynamicSharedMemorySize, SMEM_TOTAL);

    // prep: f32 -> f16 copies (memory-bound, ~60us total)
    prep_f16_kernel<<<X_ELEMS / 8 / 256, 256>>>((const float4*)input_word,
                                                (uint4*)pX, X_ELEMS / 8);
    prep_f16_kernel<<<X_ELEMS / 8 / 256, 256>>>((const float4*)hidden,
                                                (uint4*)pH, X_ELEMS / 8);
    prep_f16_kernel<<<W_ELEMS / 8 / 256, 256>>>((const float4*)Wx,
                                                (uint4*)pWx, W_ELEMS / 8);
    prep_f16_kernel<<<W_ELEMS / 8 / 256, 256>>>((const float4*)Wh,
                                                (uint4*)pWh, W_ELEMS / 8);

    dim3 grid(B_DIM / BM, N_DIM / BN);   // (32, 256), M fastest
    gate_mma_kernel<<<grid, 256, SMEM_TOTAL>>>(pX, pH, pWx, bx, pWh, (float*)d_out);
}

// round 14
// speedup vs baseline: 1.0723x; 1.0034x over previous
#include <cuda_runtime.h>
#include <cuda_fp16.h>
#include <cstdint>
#include <math.h>

// ---------------- problem dims ----------------
#define C_DIM  16
#define B_DIM  4096
#define N_DIM  32768           // C * 2H
#define K_HALF 1024

#define X_ELEMS (B_DIM * K_HALF)      //  4 M
#define W_ELEMS (N_DIM * K_HALF)      // 32 M
#define X8 (X_ELEMS / 8)              // 524288
#define W8 (W_ELEMS / 8)              // 4194304
#define TOTAL8 (2 * W8 + 2 * X8)      // 9437184 = 36864 * 256

// ---------------- tiling (best known shape) ----------------
#define BM 128
#define BN 128
#define BKE 64                 // K elements per slab (64 halves = 128B row)
#define NSTAGE 3
#define NITER 32               // 2048 / 64

#define A_TILE_BYTES (BM * 128)        // 16384
#define B_TILE_BYTES (BN * 128)        // 16384
#define STAGE_BYTES  (A_TILE_BYTES + B_TILE_BYTES)   // 32768
#define SMEM_TOTAL   (NSTAGE * STAGE_BYTES)          // 98304

static const size_t HALF_OUT = (size_t)B_DIM * C_DIM * 1024;

// ---------------- f16 scratch (device globals: allowed) ----------------
__device__ __half g_X[X_ELEMS];
__device__ __half g_H[X_ELEMS];
__device__ __half g_Wx[W_ELEMS];
__device__ __half g_Wh[W_ELEMS];

__device__ __forceinline__ uint32_t smem_u32(const void* p) {
    uint32_t a;
    asm("{ .reg .u64 t; cvta.to.shared.u64 t, %1; cvt.u32.u64 %0, t; }" : "=r"(a) : "l"(p));
    return a;
}

#define CP_ASYNC16(dst, src) \
    asm volatile("cp.async.cg.shared.global [%0], [%1], 16;" :: "r"(dst), "l"(src))
#define CP_COMMIT() asm volatile("cp.async.commit_group;")
#define CP_WAIT1()  asm volatile("cp.async.wait_group 1;")

#define LDSM_X4(r0, r1, r2, r3, a) \
    asm volatile("ldmatrix.sync.aligned.m8n8.x4.shared.b16 {%0,%1,%2,%3}, [%4];" \
                 : "=r"(r0), "=r"(r1), "=r"(r2), "=r"(r3) : "r"(a))

// m16n8k16 f16 MMA, fp32 accumulate
#define MMA_F16(c, a, b0, b1)                                                    \
    asm volatile("mma.sync.aligned.m16n8k16.row.col.f32.f16.f16.f32 "            \
                 "{%0,%1,%2,%3}, {%4,%5,%6,%7}, {%8,%9}, {%0,%1,%2,%3};"         \
                 : "+f"((c)[0]), "+f"((c)[1]), "+f"((c)[2]), "+f"((c)[3])        \
                 : "r"((a)[0]), "r"((a)[1]), "r"((a)[2]), "r"((a)[3]),           \
                   "r"(b0), "r"(b1))

// ---------------- fused prep: all 4 buffers in ONE launch ----------------
__global__ void __launch_bounds__(256)
prep_all_kernel(const float4* __restrict__ sWx, const float4* __restrict__ sWh,
                const float4* __restrict__ sX,  const float4* __restrict__ sH,
                uint4* __restrict__ dWx, uint4* __restrict__ dWh,
                uint4* __restrict__ dX,  uint4* __restrict__ dH) {
    const int i = blockIdx.x * blockDim.x + threadIdx.x;   // < TOTAL8 exactly
    const float4* s;
    uint4* d;
    int j;
    if (i < W8)               { s = sWx; d = dWx; j = i; }
    else if (i < 2 * W8)      { s = sWh; d = dWh; j = i - W8; }
    else if (i < 2 * W8 + X8) { s = sX;  d = dX;  j = i - 2 * W8; }
    else                      { s = sH;  d = dH;  j = i - 2 * W8 - X8; }

    float4 v0 = s[2 * j], v1 = s[2 * j + 1];
    __half2 h0 = __floats2half2_rn(v0.x, v0.y);
    __half2 h1 = __floats2half2_rn(v0.z, v0.w);
    __half2 h2 = __floats2half2_rn(v1.x, v1.y);
    __half2 h3 = __floats2half2_rn(v1.z, v1.w);
    uint4 o;
    o.x = *(uint32_t*)&h0; o.y = *(uint32_t*)&h1;
    o.z = *(uint32_t*)&h2; o.w = *(uint32_t*)&h3;
    d[j] = o;
}

// ------- main GEMM: f16 m16n8k16, 64x32 warp tiles, frag double-buffer -------
__global__ void __launch_bounds__(256, 2)
gate_mma_kernel(const __half* __restrict__ Xh,   // [4096, 1024]
                const __half* __restrict__ Hh,   // [4096, 1024]
                const __half* __restrict__ Wxh,  // [32768, 1024]
                const float*  __restrict__ bx,   // [32768]
                const __half* __restrict__ Whh,  // [32768, 1024]
                float* __restrict__ out)
{
    extern __shared__ char smem[];
    const uint32_t sb = smem_u32(smem);

    const int tid  = threadIdx.x;
    const int lane = tid & 31;
    const int warp = tid >> 5;
    const int wm   = warp >> 2;          // 0..1
    const int wn   = warp & 3;           // 0..3

    const int bm = blockIdx.x * BM;      // M fastest: A tiles L2-resident
    const int bn = blockIdx.y * BN;

    // ---- cp.async mapping ----
    const int lm = tid >> 1;             // tile row 0..127
    const int lk = (tid & 1) * 4;        // chunk base 0 or 4 (of 8 per row)

    // ---- ldmatrix per-lane address pieces (chunk = 16B = 8 halves = K8) ----
    const int l7 = lane & 7;
    const int am_off = l7 + ((lane >> 3) & 1) * 8;   // A rows: q1,q3 -> +8
    const int aq     = (lane >> 4) & 1;              // A: q2,q3 -> chunk+1
    const int bn_off = l7 + ((lane >> 4) & 1) * 8;   // B rows: q2,q3 -> +8
    const int bq     = (lane >> 3) & 1;              // B: q1,q3 -> chunk+1

    float acc[4][4][4];
    #pragma unroll
    for (int i = 0; i < 4; i++)
        #pragma unroll
        for (int j = 0; j < 4; j++)
            #pragma unroll
            for (int k = 0; k < 4; k++)
                acc[i][j][k] = 0.f;

    // ---- stage loader (write swizzle keyed on DEST ROW lm&7) ----
    auto load_stage = [&](int s, int it) {
        const __half* Ab = (it < 16) ? Xh : Hh;
        const __half* Bb = (it < 16) ? Wxh : Whh;
        const int k0 = (it & 15) * BKE;
        const __half* asrc = Ab + (size_t)(bm + lm) * K_HALF + k0;
        const __half* bsrc = Bb + (size_t)(bn + lm) * K_HALF + k0;
        const uint32_t arow = sb + s * STAGE_BYTES + lm * 128;
        const uint32_t brow = sb + s * STAGE_BYTES + A_TILE_BYTES + lm * 128;
        #pragma unroll
        for (int j = 0; j < 4; j++) {
            const int kc = lk + j;
            const int sw = (kc ^ (lm & 7)) << 4;
            CP_ASYNC16(arow + sw, asrc + kc * 8);
            CP_ASYNC16(brow + sw, bsrc + kc * 8);
        }
    };

    // ---- prologue ----
    load_stage(0, 0); CP_COMMIT();
    load_stage(1, 1); CP_COMMIT();

    // double-buffered fragment sets: hide LDSM latency under MMA bursts
    uint32_t ar[2][4][4], br[2][2][4];

    // ---- mainloop: one barrier per iteration ----
    #pragma unroll 1
    for (int it = 0; it < NITER; it++) {
        CP_WAIT1();
        __syncthreads();   // all warps done reading stage (it-1): safe to refill

        if (it + 2 < NITER) load_stage((it + 2) % NSTAGE, it + 2);
        CP_COMMIT();       // empty groups keep wait_group(1) semantics exact

        const int s = it % NSTAGE;
        const uint32_t a_base = sb + s * STAGE_BYTES;
        const uint32_t b_base = a_base + A_TILE_BYTES;

        // preload ks=0 fragments into buffer 0
        #pragma unroll
        for (int mf = 0; mf < 4; mf++) {
            const int m = wm * 64 + mf * 16 + am_off;
            LDSM_X4(ar[0][mf][0], ar[0][mf][1], ar[0][mf][2], ar[0][mf][3],
                    a_base + m * 128 + ((aq ^ l7) << 4));
        }
        #pragma unroll
        for (int j = 0; j < 2; j++) {
            const int n = wn * 32 + j * 16 + bn_off;
            LDSM_X4(br[0][j][0], br[0][j][1], br[0][j][2], br[0][j][3],
                    b_base + n * 128 + ((bq ^ l7) << 4));
        }

        #pragma unroll
        for (int ks = 0; ks < 4; ks++) {     // 4 x K16 = K64 per stage
            const int cur = ks & 1, nxt = cur ^ 1;

            // prefetch ks+1's fragments (overlaps with this ks's MMA burst)
            if (ks < 3) {
                #pragma unroll
                for (int mf = 0; mf < 4; mf++) {
                    const int m = wm * 64 + mf * 16 + am_off;
                    LDSM_X4(ar[nxt][mf][0], ar[nxt][mf][1], ar[nxt][mf][2], ar[nxt][mf][3],
                            a_base + m * 128 + (((2 * (ks + 1) + aq) ^ l7) << 4));
                }
                #pragma unroll
                for (int j = 0; j < 2; j++) {
                    const int n = wn * 32 + j * 16 + bn_off;
                    LDSM_X4(br[nxt][j][0], br[nxt][j][1], br[nxt][j][2], br[nxt][j][3],
                            b_base + n * 128 + (((2 * (ks + 1) + bq) ^ l7) << 4));
                }
            }

            #pragma unroll
            for (int mf = 0; mf < 4; mf++) {
                #pragma unroll
                for (int nf = 0; nf < 4; nf++) {
                    const int j = nf >> 1, h = (nf & 1) * 2;
                    MMA_F16(acc[mf][nf], ar[cur][mf], br[cur][j][h], br[cur][j][h + 1]);
                }
            }
        }
    }

    // ---- epilogue: bias + activation + scatter ----
    const int  c_blk   = bn >> 11;
    const bool is_gate = (bn & 2047) < 1024;        // sigmoid half -> input_gate
    const int  o_tile  = bn & 1023;
    float* obase = is_gate ? (out + HALF_OUT) : out;

    #pragma unroll
    for (int mf = 0; mf < 4; mf++) {
        const int m0 = bm + wm * 64 + mf * 16 + (lane >> 2);
        #pragma unroll
        for (int nf = 0; nf < 4; nf++) {
            const int n_loc = wn * 32 + nf * 8 + (lane & 3) * 2;
            const float b0 = __ldg(bx + bn + n_loc);
            const float b1 = __ldg(bx + bn + n_loc + 1);
            const int o = o_tile + n_loc;
            #pragma unroll
            for (int h = 0; h < 2; h++) {            // rows m0, m0+8
                const int m = m0 + h * 8;
                float x0 = acc[mf][nf][h * 2 + 0] + b0;
                float x1 = acc[mf][nf][h * 2 + 1] + b1;
                float2 v;
                if (is_gate) {
                    v.x = 1.f / (1.f + __expf(-x0));
                    v.y = 1.f / (1.f + __expf(-x1));
                } else {
                    v.x = 2.f / (1.f + __expf(-2.f * x0)) - 1.f;
                    v.y = 2.f / (1.f + __expf(-2.f * x1)) - 1.f;
                }
                *(float2*)(obase + ((size_t)m * C_DIM + c_blk) * 1024 + o) = v;
            }
        }
    }
}

extern "C" void kernel_launch(void* const* d_in, const int* in_sizes, int n_in,
                              void* d_out, int out_size) {
    const float* input_word = (const float*)d_in[0];
    const float* hidden     = (const float*)d_in[1];
    const float* Wx         = (const float*)d_in[2];
    const float* bx         = (const float*)d_in[3];
    const float* Wh         = (const float*)d_in[4];

    __half *pX, *pH, *pWx, *pWh;
    cudaGetSymbolAddress((void**)&pX,  g_X);
    cudaGetSymbolAddress((void**)&pH,  g_H);
    cudaGetSymbolAddress((void**)&pWx, g_Wx);
    cudaGetSymbolAddress((void**)&pWh, g_Wh);
    cudaFuncSetAttribute(gate_mma_kernel,
                         cudaFuncAttributeMaxDynamicSharedMemorySize, SMEM_TOTAL);

    // fused prep: all four f32 -> f16 conversions in one launch (~55us)
    prep_all_kernel<<<TOTAL8 / 256, 256>>>(
        (const float4*)Wx, (const float4*)Wh,
        (const float4*)input_word, (const float4*)hidden,
        (uint4*)pWx, (uint4*)pWh, (uint4*)pX, (uint4*)pH);

    dim3 grid(B_DIM / BM, N_DIM / BN);   // (32, 256), M fastest
    gate_mma_kernel<<<grid, 256, SMEM_TOTAL>>>(pX, pH, pWx, bx, pWh, (float*)d_out);
}